// round 14
// baseline (speedup 1.0000x reference)
#include <cuda_runtime.h>
#include <cuda_fp16.h>
#include <cstdint>

#define CDIM 256
#define HW 4096
#define NPIX 65536
#define NTILES 512
#define KCODES 1024
#define LOSS_OFF 16777216
#define IDX_OFF  16777217

// scratch (__device__ globals; no cudaMalloc allowed)
__device__ __half  g_A[(size_t)NPIX * 512];     // [pixel][xh(256)|xl(256)]   64 MB
__device__ __half  g_B[(size_t)KCODES * 768];   // [code][Eh|Eh|El]           1.5 MB
__device__ float   g_s1[NPIX];
__device__ float   g_s2[KCODES];
__device__ float   g_cand_d[NPIX * 4];
__device__ int     g_cand_i[NPIX * 4];
__device__ double  g_partial[NTILES];

__device__ __forceinline__ uint32_t smem_u32(const void* p) {
    uint32_t a;
    asm("{ .reg .u64 t; cvta.to.shared.u64 t, %1; cvt.u32.u64 %0, t; }" : "=r"(a) : "l"(p));
    return a;
}

#define LDSM4(r0, r1, r2, r3, addr) \
    asm volatile("ldmatrix.sync.aligned.m8n8.x4.shared.b16 {%0,%1,%2,%3}, [%4];" \
        : "=r"(r0), "=r"(r1), "=r"(r2), "=r"(r3) : "r"(addr))

#define MMA16816(c0, c1, c2, c3, a0, a1, a2, a3, b0, b1) \
    asm volatile("mma.sync.aligned.m16n8k16.row.col.f32.f16.f16.f32 " \
        "{%0,%1,%2,%3}, {%4,%5,%6,%7}, {%8,%9}, {%0,%1,%2,%3};" \
        : "+f"(c0), "+f"(c1), "+f"(c2), "+f"(c3) \
        : "r"(a0), "r"(a1), "r"(a2), "r"(a3), "r"(b0), "r"(b1))

__global__ void k_nop() {}

// ---------------------------------------------------------------------------
// split codebook: warp-per-code, coalesced   (proven R11)
// ---------------------------------------------------------------------------
__global__ void __launch_bounds__(256)
k_split_b(const float* __restrict__ cb, __half* __restrict__ B_,
          float* __restrict__ s2g) {
    const int gw = (blockIdx.x * 256 + threadIdx.x) >> 5;   // global warp = code
    const int l  = threadIdx.x & 31;
    if (gw >= KCODES) return;
    const float* row = cb + (size_t)gw * CDIM;
    __half* o = B_ + (size_t)gw * 768;
    float e[8];
    float s = 0.f;
    #pragma unroll
    for (int j = 0; j < 8; ++j) {
        e[j] = row[l + 32 * j];
        s += e[j] * e[j];
    }
    #pragma unroll
    for (int off = 16; off > 0; off >>= 1)
        s += __shfl_down_sync(0xffffffffu, s, off);
    if (l == 0) s2g[gw] = s;
    #pragma unroll
    for (int j = 0; j < 8; ++j) {
        int d = l + 32 * j;
        float E = e[j] * 1024.0f;
        __half eh = __float2half_rn(E);
        __half el = __float2half_rn(E - __half2float(eh));
        o[d] = eh; o[256 + d] = eh; o[512 + d] = el;
    }
}

// ---------------------------------------------------------------------------
// split inputs -> fp16 hi/lo [pixel][d]; s1 sequential-d   (proven R13)
// ---------------------------------------------------------------------------
__global__ void __launch_bounds__(256)
k_split_a(const float* __restrict__ in, __half* __restrict__ A_,
          float* __restrict__ s1g) {
    extern __shared__ float xs[];   // [256 d][stride 37]
    const int tid = threadIdx.x;
    const int blk = blockIdx.x;                 // 2048 blocks of 32 pixels
    const int b = blk >> 7, hw0 = (blk & 127) << 5;
    const float* inb = in + ((size_t)b << 20);

    for (int t = tid; t < 256 * 8; t += 256) {
        int d = t >> 3, p4 = t & 7;
        float4 v = *(const float4*)(inb + (size_t)d * HW + hw0 + p4 * 4);
        float* dst = xs + d * 37 + p4 * 4;
        dst[0] = v.x; dst[1] = v.y; dst[2] = v.z; dst[3] = v.w;
    }
    __syncthreads();

    if (tid < 32) {   // sequential-d order -> bit-identical s1
        float s = 0.f;
        for (int d = 0; d < CDIM; ++d) { float v = xs[d * 37 + tid]; s += v * v; }
        s1g[blk * 32 + tid] = s;
    }

    const int h = tid >> 7, t = tid & 127;
    const int d0 = 2 * t;
    for (int i = 16 * h; i < 16 * h + 16; ++i) {
        float x0 = xs[d0 * 37 + i];
        float x1 = xs[(d0 + 1) * 37 + i];
        __half xh0 = __float2half_rn(x0);
        __half xh1 = __float2half_rn(x1);
        __half xl0 = __float2half_rn(x0 - __half2float(xh0));
        __half xl1 = __float2half_rn(x1 - __half2float(xh1));
        size_t row = ((size_t)(blk * 32 + i)) << 9;   // *512
        *(__half2*)(A_ + row + d0)       = __halves2half2(xh0, xh1);
        *(__half2*)(A_ + row + 256 + d0) = __halves2half2(xl0, xl1);
    }
}

// ---------------------------------------------------------------------------
// HMMA GEMM tile: 128 px x 256 codes; 256 thr (8 warps, 2M x 4N), warp tile
// 64x64 (per-warp code identical to proven R10). 3-stage pipeline, one sync.
// smem: [0,2K) rd | [2K,4K) ri | [4K,5K) s2 | [8K) 3 x 49152 stages
// stage: A 128x128B @0 | B 256x128B @16384; swizzle seg^((row&7)<<4)
// ---------------------------------------------------------------------------
__device__ __forceinline__ void load_chunk3(uint32_t st, const char* Ag, const char* Bg,
                                            int p0, int nt, int kc, int tid) {
    const size_t aoff = (size_t)(kc & 7) * 128;
    const size_t boff = (size_t)kc * 128;
    #pragma unroll
    for (int i = 0; i < 4; ++i) {
        int o = tid + 256 * i;           // 0..1023  (A: 128 rows x 8 segs)
        int row = o >> 3, seg = (o & 7) * 16;
        const char* src = Ag + ((size_t)(p0 + row) << 10) + aoff + seg;
        uint32_t dst = st + row * 128 + (seg ^ ((row & 7) << 4));
        asm volatile("cp.async.cg.shared.global [%0], [%1], 16;" :: "r"(dst), "l"(src));
    }
    #pragma unroll
    for (int i = 0; i < 8; ++i) {
        int o = tid + 256 * i;           // 0..2047  (B: 256 rows x 8 segs)
        int row = o >> 3, seg = (o & 7) * 16;
        const char* src = Bg + (size_t)(nt * 256 + row) * 1536 + boff + seg;
        uint32_t dst = st + 16384 + row * 128 + (seg ^ ((row & 7) << 4));
        asm volatile("cp.async.cg.shared.global [%0], [%1], 16;" :: "r"(dst), "l"(src));
    }
}

__global__ void __launch_bounds__(256, 1)
k_gemm(const __half* __restrict__ Ah, const __half* __restrict__ Bh,
       const float* __restrict__ s1g, const float* __restrict__ s2g,
       float* __restrict__ cand_d, int* __restrict__ cand_i) {
    extern __shared__ char sm[];
    uint32_t sb = smem_u32(sm);
    float* rd = (float*)sm;                 // 128*4 floats
    int*   ri = (int*)(sm + 2048);          // 128*4 ints
    float* s2s = (float*)(sm + 4096);       // 256 floats
    const uint32_t stg = sb + 8192;

    const int tid = threadIdx.x, lane = tid & 31, wid = tid >> 5;
    const int warp_m = wid & 1, warp_n = wid >> 1;    // 2M x 4N warp grid
    const int m0 = warp_m * 64, n0 = warp_n * 64;
    const int blk = blockIdx.x, pb = blk >> 2, nt = blk & 3;   // 4 tiles of 256 codes
    const int p0 = pb * 128;
    const char* Ag = (const char*)Ah;
    const char* Bg = (const char*)Bh;

    s2s[tid] = s2g[nt * 256 + tid];

    const int rA = (lane & 7) + ((lane >> 3) & 1) * 8;
    const int cA = (lane >> 4) * 16;
    const int mA = (rA & 7) << 4;
    uint32_t arow[4];
    #pragma unroll
    for (int f = 0; f < 4; ++f) arow[f] = (uint32_t)(m0 + f * 16 + rA) * 128;
    const int rB = (lane & 7) + ((lane >> 4) << 3);
    const int cB = ((lane >> 3) & 1) * 16;
    const int mB = (rB & 7) << 4;
    uint32_t brow[4];
    #pragma unroll
    for (int g = 0; g < 4; ++g) brow[g] = (uint32_t)(n0 + g * 16 + rB) * 128;

    float s1v[8];
    #pragma unroll
    for (int s = 0; s < 8; ++s)
        s1v[s] = s1g[p0 + m0 + (s >> 1) * 16 + (lane >> 2) + (s & 1) * 8];

    float c[4][8][4];
    #pragma unroll
    for (int mf = 0; mf < 4; ++mf)
        #pragma unroll
        for (int j = 0; j < 8; ++j)
            #pragma unroll
            for (int q = 0; q < 4; ++q) c[mf][j][q] = 0.f;

    load_chunk3(stg,         Ag, Bg, p0, nt, 0, tid);
    asm volatile("cp.async.commit_group;" ::: "memory");
    load_chunk3(stg + 49152, Ag, Bg, p0, nt, 1, tid);
    asm volatile("cp.async.commit_group;" ::: "memory");

    for (int kc = 0; kc < 12; ++kc) {
        if (kc < 11) asm volatile("cp.async.wait_group 1;" ::: "memory");
        else         asm volatile("cp.async.wait_group 0;" ::: "memory");
        __syncthreads();
        if (kc + 2 < 12) {
            load_chunk3(stg + ((kc + 2) % 3) * 49152, Ag, Bg, p0, nt, kc + 2, tid);
            asm volatile("cp.async.commit_group;" ::: "memory");
        }

        const uint32_t sA = stg + (kc % 3) * 49152;
        const uint32_t sB = sA + 16384;
        #pragma unroll
        for (int ks = 0; ks < 4; ++ks) {
            const uint32_t colA = (uint32_t)((cA + ks * 32) ^ mA);
            const uint32_t colB = (uint32_t)((cB + ks * 32) ^ mB);
            uint32_t a[4][4], bf[4][4];
            #pragma unroll
            for (int f = 0; f < 4; ++f)
                LDSM4(a[f][0], a[f][1], a[f][2], a[f][3], sA + arow[f] + colA);
            #pragma unroll
            for (int g = 0; g < 4; ++g)
                LDSM4(bf[g][0], bf[g][1], bf[g][2], bf[g][3], sB + brow[g] + colB);

            #pragma unroll
            for (int f = 0; f < 4; ++f) {
                #pragma unroll
                for (int g = 0; g < 4; ++g) {
                    MMA16816(c[f][2*g][0], c[f][2*g][1], c[f][2*g][2], c[f][2*g][3],
                             a[f][0], a[f][1], a[f][2], a[f][3], bf[g][0], bf[g][1]);
                    MMA16816(c[f][2*g+1][0], c[f][2*g+1][1], c[f][2*g+1][2], c[f][2*g+1][3],
                             a[f][0], a[f][1], a[f][2], a[f][3], bf[g][2], bf[g][3]);
                }
            }
        }
    }

    // fold into per-thread argmin (ascending local n -> first-index tie-break)
    const float SC = 0.001953125f;   // 2^-9
    float bd[8];
    int   bi[8];
    #pragma unroll
    for (int s = 0; s < 8; ++s) { bd[s] = 3.4e38f; bi[s] = 0; }
    #pragma unroll
    for (int mf = 0; mf < 4; ++mf) {
        #pragma unroll
        for (int j = 0; j < 8; ++j) {
            const int nl = n0 + j * 8 + ((lane & 3) << 1);
            const float s2a = s2s[nl], s2b = s2s[nl + 1];
            const int sl0 = mf * 2, sl1 = mf * 2 + 1;
            float d0 = (s1v[sl0] + s2a) - c[mf][j][0] * SC;
            float d1 = (s1v[sl0] + s2b) - c[mf][j][1] * SC;
            float d2 = (s1v[sl1] + s2a) - c[mf][j][2] * SC;
            float d3 = (s1v[sl1] + s2b) - c[mf][j][3] * SC;
            if (d0 < bd[sl0]) { bd[sl0] = d0; bi[sl0] = nl; }
            if (d1 < bd[sl0]) { bd[sl0] = d1; bi[sl0] = nl + 1; }
            if (d2 < bd[sl1]) { bd[sl1] = d2; bi[sl1] = nl; }
            if (d3 < bd[sl1]) { bd[sl1] = d3; bi[sl1] = nl + 1; }
        }
    }
    #pragma unroll
    for (int s = 0; s < 8; ++s) {
        #pragma unroll
        for (int off = 1; off <= 2; off <<= 1) {
            float od = __shfl_xor_sync(0xffffffffu, bd[s], off);
            int   oi = __shfl_xor_sync(0xffffffffu, bi[s], off);
            if (od < bd[s] || (od == bd[s] && oi < bi[s])) { bd[s] = od; bi[s] = oi; }
        }
    }
    __syncthreads();
    if ((lane & 3) == 0) {
        #pragma unroll
        for (int s = 0; s < 8; ++s) {
            int row = m0 + (s >> 1) * 16 + (lane >> 2) + (s & 1) * 8;
            rd[row * 4 + warp_n] = bd[s];
            ri[row * 4 + warp_n] = bi[s];
        }
    }
    __syncthreads();
    if (tid < 128) {
        float bdv = rd[tid * 4]; int biv = ri[tid * 4];
        #pragma unroll
        for (int t = 1; t < 4; ++t) {   // ascending warp_n = ascending code
            float d = rd[tid * 4 + t]; int i = ri[tid * 4 + t];
            if (d < bdv || (d == bdv && i < biv)) { bdv = d; biv = i; }
        }
        cand_d[(size_t)(p0 + tid) * 4 + nt] = bdv;
        cand_i[(size_t)(p0 + tid) * 4 + nt] = nt * 256 + biv;
    }
}

// ---------------------------------------------------------------------------
// fused: combine 4 candidates -> index + loss partial + sector-efficient
// gather (proven R13 body, candidate count 8 -> 4)
// ---------------------------------------------------------------------------
__global__ void __launch_bounds__(256)
k_out(const float* __restrict__ cb,
      const float* __restrict__ cand_d, const int* __restrict__ cand_i,
      float* __restrict__ out, double* __restrict__ partial) {
    extern __shared__ float qs[];        // [64][257]
    __shared__ int idxs[128];
    __shared__ float sd[128];
    __shared__ double red[256];
    const int tid = threadIdx.x;
    const int w = tid >> 5, l = tid & 31;
    const int blk = blockIdx.x;
    const int b = blk >> 5, hw0 = (blk & 31) << 7;

    if (tid < 128) {
        const int pp = blk * 128 + tid;   // flat pixel index
        size_t base = (size_t)pp * 4;
        float bdv = cand_d[base]; int biv = cand_i[base];
        #pragma unroll
        for (int t = 1; t < 4; ++t) {
            float d = cand_d[base + t]; int i = cand_i[base + t];
            if (d < bdv || (d == bdv && i < biv)) { bdv = d; biv = i; }
        }
        idxs[tid] = biv;
        sd[tid] = bdv;
        out[IDX_OFF + pp] = (float)biv;
    }
    __syncthreads();

    red[tid] = (tid < 128) ? (double)sd[tid] : 0.0;
    __syncthreads();
    #pragma unroll
    for (int s = 128; s > 0; s >>= 1) {
        if (tid < s) red[tid] += red[tid + s];
        __syncthreads();
    }
    if (tid == 0) partial[blk] = red[0];

    float* outb = out + ((size_t)b << 20);
    #pragma unroll
    for (int h = 0; h < 2; ++h) {
        #pragma unroll
        for (int r = 0; r < 8; ++r) {
            const int lp = w * 8 + r;
            const float* row = cb + (size_t)idxs[h * 64 + lp] * CDIM;
            float* q = qs + lp * 257;
            #pragma unroll
            for (int j = 0; j < 8; ++j)
                q[l + 32 * j] = row[l + 32 * j];
        }
        __syncthreads();
        for (int t = tid; t < 4096; t += 256) {
            int d = t >> 4, p4 = t & 15;
            float4 v;
            v.x = qs[(4 * p4 + 0) * 257 + d];
            v.y = qs[(4 * p4 + 1) * 257 + d];
            v.z = qs[(4 * p4 + 2) * 257 + d];
            v.w = qs[(4 * p4 + 3) * 257 + d];
            *(float4*)(outb + (size_t)d * HW + hw0 + h * 64 + 4 * p4) = v;
        }
        __syncthreads();
    }
}

__global__ void k_final(const double* __restrict__ partial, float* __restrict__ out) {
    __shared__ double red[256];
    int tid = threadIdx.x;
    red[tid] = partial[tid] + partial[tid + 256];
    __syncthreads();
    #pragma unroll
    for (int s = 128; s > 0; s >>= 1) {
        if (tid < s) red[tid] += red[tid + s];
        __syncthreads();
    }
    if (tid == 0) {
        double mse = red[0] / ((double)NPIX * (double)CDIM);
        out[LOSS_OFF] = (float)(1.25 * mse);
    }
}

// ---------------------------------------------------------------------------
extern "C" void kernel_launch(void* const* d_in, const int* in_sizes, int n_in,
                              void* d_out, int out_size) {
    (void)in_sizes; (void)n_in; (void)out_size;
    const float* in = (const float*)d_in[0];
    const float* cb = (const float*)d_in[1];
    float* out = (float*)d_out;

    __half* A_p; __half* B_p;
    float *s1_p, *s2_p, *cd_p; int* ci_p; double* part_p;
    cudaGetSymbolAddress((void**)&A_p,   g_A);
    cudaGetSymbolAddress((void**)&B_p,   g_B);
    cudaGetSymbolAddress((void**)&s1_p,  g_s1);
    cudaGetSymbolAddress((void**)&s2_p,  g_s2);
    cudaGetSymbolAddress((void**)&cd_p,  g_cand_d);
    cudaGetSymbolAddress((void**)&ci_p,  g_cand_i);
    cudaGetSymbolAddress((void**)&part_p, g_partial);

    const int smem_a = 256 * 37 * 4;             // 37888
    const int smem_g = 8192 + 3 * 49152;         // 155648
    const int smem_o = 64 * 257 * 4;             // 65792
    cudaFuncSetAttribute(k_split_a, cudaFuncAttributeMaxDynamicSharedMemorySize, smem_a);
    cudaFuncSetAttribute(k_gemm,    cudaFuncAttributeMaxDynamicSharedMemorySize, smem_g);
    cudaFuncSetAttribute(k_out,     cudaFuncAttributeMaxDynamicSharedMemorySize, smem_o);

    k_split_b<<<128, 256>>>(cb, B_p, s2_p);                           // idx 0
    k_split_a<<<2048, 256, smem_a>>>(in, A_p, s1_p);                  // idx 1
    k_nop<<<1, 32>>>();                                               // idx 2
    k_gemm<<<2048, 256, smem_g>>>(A_p, B_p, s1_p, s2_p, cd_p, ci_p);  // idx 3 -> ncu
    k_out<<<NTILES, 256, smem_o>>>(cb, cd_p, ci_p, out, part_p);      // idx 4
    k_final<<<1, 256>>>(part_p, out);                                 // idx 5
}

// round 15
// speedup vs baseline: 1.0654x; 1.0654x over previous
#include <cuda_runtime.h>
#include <cuda_fp16.h>
#include <cstdint>

#define CDIM 256
#define HW 4096
#define NPIX 65536
#define NTILES 512
#define KCODES 1024
#define LOSS_OFF 16777216
#define IDX_OFF  16777217

// scratch (__device__ globals; no cudaMalloc allowed)
__device__ __half  g_A[(size_t)NPIX * 512];     // [pixel][xh(256)|xl(256)]   64 MB
__device__ __half  g_B[(size_t)KCODES * 768];   // [code][Eh|Eh|El]           1.5 MB
__device__ float   g_s1[NPIX];
__device__ float   g_s2[KCODES];
__device__ float   g_cand_d[NPIX * 4];
__device__ int     g_cand_i[NPIX * 4];
__device__ double  g_partial[NTILES];

__device__ __forceinline__ uint32_t smem_u32(const void* p) {
    uint32_t a;
    asm("{ .reg .u64 t; cvta.to.shared.u64 t, %1; cvt.u32.u64 %0, t; }" : "=r"(a) : "l"(p));
    return a;
}

#define LDSM4(r0, r1, r2, r3, addr) \
    asm volatile("ldmatrix.sync.aligned.m8n8.x4.shared.b16 {%0,%1,%2,%3}, [%4];" \
        : "=r"(r0), "=r"(r1), "=r"(r2), "=r"(r3) : "r"(addr))

#define MMA16816(c0, c1, c2, c3, a0, a1, a2, a3, b0, b1) \
    asm volatile("mma.sync.aligned.m16n8k16.row.col.f32.f16.f16.f32 " \
        "{%0,%1,%2,%3}, {%4,%5,%6,%7}, {%8,%9}, {%0,%1,%2,%3};" \
        : "+f"(c0), "+f"(c1), "+f"(c2), "+f"(c3) \
        : "r"(a0), "r"(a1), "r"(a2), "r"(a3), "r"(b0), "r"(b1))

__global__ void k_nop() {}

// ---------------------------------------------------------------------------
// split codebook: warp-per-code, coalesced   (proven R11)
// ---------------------------------------------------------------------------
__global__ void __launch_bounds__(256)
k_split_b(const float* __restrict__ cb, __half* __restrict__ B_,
          float* __restrict__ s2g) {
    const int gw = (blockIdx.x * 256 + threadIdx.x) >> 5;   // global warp = code
    const int l  = threadIdx.x & 31;
    if (gw >= KCODES) return;
    const float* row = cb + (size_t)gw * CDIM;
    __half* o = B_ + (size_t)gw * 768;
    float e[8];
    float s = 0.f;
    #pragma unroll
    for (int j = 0; j < 8; ++j) {
        e[j] = row[l + 32 * j];
        s += e[j] * e[j];
    }
    #pragma unroll
    for (int off = 16; off > 0; off >>= 1)
        s += __shfl_down_sync(0xffffffffu, s, off);
    if (l == 0) s2g[gw] = s;
    #pragma unroll
    for (int j = 0; j < 8; ++j) {
        int d = l + 32 * j;
        float E = e[j] * 1024.0f;
        __half eh = __float2half_rn(E);
        __half el = __float2half_rn(E - __half2float(eh));
        o[d] = eh; o[256 + d] = eh; o[512 + d] = el;
    }
}

// ---------------------------------------------------------------------------
// split inputs -> fp16 hi/lo [pixel][d]; s1 sequential-d   (proven R13)
// ---------------------------------------------------------------------------
__global__ void __launch_bounds__(256)
k_split_a(const float* __restrict__ in, __half* __restrict__ A_,
          float* __restrict__ s1g) {
    extern __shared__ float xs[];   // [256 d][stride 37]
    const int tid = threadIdx.x;
    const int blk = blockIdx.x;                 // 2048 blocks of 32 pixels
    const int b = blk >> 7, hw0 = (blk & 127) << 5;
    const float* inb = in + ((size_t)b << 20);

    for (int t = tid; t < 256 * 8; t += 256) {
        int d = t >> 3, p4 = t & 7;
        float4 v = *(const float4*)(inb + (size_t)d * HW + hw0 + p4 * 4);
        float* dst = xs + d * 37 + p4 * 4;
        dst[0] = v.x; dst[1] = v.y; dst[2] = v.z; dst[3] = v.w;
    }
    __syncthreads();

    if (tid < 32) {   // sequential-d order -> bit-identical s1
        float s = 0.f;
        for (int d = 0; d < CDIM; ++d) { float v = xs[d * 37 + tid]; s += v * v; }
        s1g[blk * 32 + tid] = s;
    }

    const int h = tid >> 7, t = tid & 127;
    const int d0 = 2 * t;
    for (int i = 16 * h; i < 16 * h + 16; ++i) {
        float x0 = xs[d0 * 37 + i];
        float x1 = xs[(d0 + 1) * 37 + i];
        __half xh0 = __float2half_rn(x0);
        __half xh1 = __float2half_rn(x1);
        __half xl0 = __float2half_rn(x0 - __half2float(xh0));
        __half xl1 = __float2half_rn(x1 - __half2float(xh1));
        size_t row = ((size_t)(blk * 32 + i)) << 9;   // *512
        *(__half2*)(A_ + row + d0)       = __halves2half2(xh0, xh1);
        *(__half2*)(A_ + row + 256 + d0) = __halves2half2(xl0, xl1);
    }
}

// ---------------------------------------------------------------------------
// HMMA GEMM: 128 px x 2 consecutive 128-code tiles per CTA (24 chunks in one
// pipeline). Per-chunk body = proven R13/R10: 4 warps, 64x64 warp tile,
// 3-stage XOR-swizzled stages, ONE __syncthreads per chunk, 2 CTAs/SM.
// smem: [0,1KB) rd | [1KB,2KB) ri | [2KB,3KB) s2 (256) | [4KB) 3 x 32768
// ---------------------------------------------------------------------------
__device__ __forceinline__ void load_chunk3(uint32_t st, const char* Ag, const char* Bg,
                                            int p0, int nt, int kc, int tid) {
    const size_t aoff = (size_t)(kc & 7) * 128;
    const size_t boff = (size_t)kc * 128;
    #pragma unroll
    for (int i = 0; i < 8; ++i) {
        int o = tid + 128 * i;           // 0..1023
        int row = o >> 3, seg = (o & 7) * 16;
        const char* src = Ag + ((size_t)(p0 + row) << 10) + aoff + seg;
        uint32_t dst = st + row * 128 + (seg ^ ((row & 7) << 4));
        asm volatile("cp.async.cg.shared.global [%0], [%1], 16;" :: "r"(dst), "l"(src));
    }
    #pragma unroll
    for (int i = 0; i < 8; ++i) {
        int o = tid + 128 * i;
        int row = o >> 3, seg = (o & 7) * 16;
        const char* src = Bg + (size_t)(nt * 128 + row) * 1536 + boff + seg;
        uint32_t dst = st + 16384 + row * 128 + (seg ^ ((row & 7) << 4));
        asm volatile("cp.async.cg.shared.global [%0], [%1], 16;" :: "r"(dst), "l"(src));
    }
}

__global__ void __launch_bounds__(128, 2)
k_gemm(const __half* __restrict__ Ah, const __half* __restrict__ Bh,
       const float* __restrict__ s1g, const float* __restrict__ s2g,
       float* __restrict__ cand_d, int* __restrict__ cand_i) {
    extern __shared__ char sm[];
    uint32_t sb = smem_u32(sm);
    float* rd = (float*)sm;
    int*   ri = (int*)(sm + 1024);
    float* s2s = (float*)(sm + 2048);       // 256 floats (two tiles)
    const uint32_t stg = sb + 4096;

    const int tid = threadIdx.x, lane = tid & 31, wid = tid >> 5;
    const int warp_m = wid & 1, warp_n = wid >> 1;    // 2M x 2N warp grid
    const int m0 = warp_m * 64, n0 = warp_n * 64;
    const int blk = blockIdx.x, pb = blk >> 2, np = blk & 3;   // 4 tile-pairs
    const int p0 = pb * 128;
    const char* Ag = (const char*)Ah;
    const char* Bg = (const char*)Bh;

    s2s[tid]       = s2g[np * 256 + tid];
    s2s[tid + 128] = s2g[np * 256 + 128 + tid];

    const int rA = (lane & 7) + ((lane >> 3) & 1) * 8;
    const int cA = (lane >> 4) * 16;
    const int mA = (rA & 7) << 4;
    uint32_t arow[4];
    #pragma unroll
    for (int f = 0; f < 4; ++f) arow[f] = (uint32_t)(m0 + f * 16 + rA) * 128;
    const int rB = (lane & 7) + ((lane >> 4) << 3);
    const int cB = ((lane >> 3) & 1) * 16;
    const int mB = (rB & 7) << 4;
    uint32_t brow[4];
    #pragma unroll
    for (int g = 0; g < 4; ++g) brow[g] = (uint32_t)(n0 + g * 16 + rB) * 128;

    float s1v[8];
    #pragma unroll
    for (int s = 0; s < 8; ++s)
        s1v[s] = s1g[p0 + m0 + (s >> 1) * 16 + (lane >> 2) + (s & 1) * 8];

    float c[4][8][4];
    #pragma unroll
    for (int mf = 0; mf < 4; ++mf)
        #pragma unroll
        for (int j = 0; j < 8; ++j)
            #pragma unroll
            for (int q = 0; q < 4; ++q) c[mf][j][q] = 0.f;

    const float SC = 0.001953125f;   // 2^-9
    float bd[8];
    int   bi[8];
    #pragma unroll
    for (int s = 0; s < 8; ++s) { bd[s] = 3.4e38f; bi[s] = 0; }

    // prologue: global chunks 0,1 (tile 2*np, kc 0,1)
    load_chunk3(stg,         Ag, Bg, p0, 2 * np, 0, tid);
    asm volatile("cp.async.commit_group;" ::: "memory");
    load_chunk3(stg + 32768, Ag, Bg, p0, 2 * np, 1, tid);
    asm volatile("cp.async.commit_group;" ::: "memory");

    for (int q = 0; q < 24; ++q) {
        if (q < 23) asm volatile("cp.async.wait_group 1;" ::: "memory");
        else        asm volatile("cp.async.wait_group 0;" ::: "memory");
        __syncthreads();
        if (q + 2 < 24) {
            const int qq = q + 2;
            load_chunk3(stg + (qq % 3) * 32768, Ag, Bg, p0,
                        2 * np + (qq >= 12), qq % 12, tid);
            asm volatile("cp.async.commit_group;" ::: "memory");
        }

        const uint32_t sA = stg + (q % 3) * 32768;
        const uint32_t sB = sA + 16384;
        #pragma unroll
        for (int ks = 0; ks < 4; ++ks) {
            const uint32_t colA = (uint32_t)((cA + ks * 32) ^ mA);
            const uint32_t colB = (uint32_t)((cB + ks * 32) ^ mB);
            uint32_t a[4][4], bf[4][4];
            #pragma unroll
            for (int f = 0; f < 4; ++f)
                LDSM4(a[f][0], a[f][1], a[f][2], a[f][3], sA + arow[f] + colA);
            #pragma unroll
            for (int g = 0; g < 4; ++g)
                LDSM4(bf[g][0], bf[g][1], bf[g][2], bf[g][3], sB + brow[g] + colB);

            #pragma unroll
            for (int f = 0; f < 4; ++f) {
                #pragma unroll
                for (int g = 0; g < 4; ++g) {
                    MMA16816(c[f][2*g][0], c[f][2*g][1], c[f][2*g][2], c[f][2*g][3],
                             a[f][0], a[f][1], a[f][2], a[f][3], bf[g][0], bf[g][1]);
                    MMA16816(c[f][2*g+1][0], c[f][2*g+1][1], c[f][2*g+1][2], c[f][2*g+1][3],
                             a[f][0], a[f][1], a[f][2], a[f][3], bf[g][2], bf[g][3]);
                }
            }
        }

        if ((q % 12) == 11) {
            // fold this tile into running argmin (global code ids, ascending)
            const int tb = (q >= 12) ? 128 : 0;
            const int nbase = (2 * np + (q >= 12)) * 128;
            #pragma unroll
            for (int mf = 0; mf < 4; ++mf) {
                #pragma unroll
                for (int j = 0; j < 8; ++j) {
                    const int nl = n0 + j * 8 + ((lane & 3) << 1);
                    const float s2a = s2s[tb + nl], s2b = s2s[tb + nl + 1];
                    const int sl0 = mf * 2, sl1 = mf * 2 + 1;
                    float d0 = (s1v[sl0] + s2a) - c[mf][j][0] * SC;
                    float d1 = (s1v[sl0] + s2b) - c[mf][j][1] * SC;
                    float d2 = (s1v[sl1] + s2a) - c[mf][j][2] * SC;
                    float d3 = (s1v[sl1] + s2b) - c[mf][j][3] * SC;
                    if (d0 < bd[sl0]) { bd[sl0] = d0; bi[sl0] = nbase + nl; }
                    if (d1 < bd[sl0]) { bd[sl0] = d1; bi[sl0] = nbase + nl + 1; }
                    if (d2 < bd[sl1]) { bd[sl1] = d2; bi[sl1] = nbase + nl; }
                    if (d3 < bd[sl1]) { bd[sl1] = d3; bi[sl1] = nbase + nl + 1; }
                    c[mf][j][0] = 0.f; c[mf][j][1] = 0.f;
                    c[mf][j][2] = 0.f; c[mf][j][3] = 0.f;
                }
            }
        }
    }

    // quad reduce (lexicographic, global code ids)
    #pragma unroll
    for (int s = 0; s < 8; ++s) {
        #pragma unroll
        for (int off = 1; off <= 2; off <<= 1) {
            float od = __shfl_xor_sync(0xffffffffu, bd[s], off);
            int   oi = __shfl_xor_sync(0xffffffffu, bi[s], off);
            if (od < bd[s] || (od == bd[s] && oi < bi[s])) { bd[s] = od; bi[s] = oi; }
        }
    }
    __syncthreads();
    if ((lane & 3) == 0) {
        #pragma unroll
        for (int s = 0; s < 8; ++s) {
            int row = m0 + (s >> 1) * 16 + (lane >> 2) + (s & 1) * 8;
            rd[row * 2 + warp_n] = bd[s];
            ri[row * 2 + warp_n] = bi[s];
        }
    }
    __syncthreads();
    {
        float d0 = rd[tid * 2], d1 = rd[tid * 2 + 1];
        int i0 = ri[tid * 2], i1 = ri[tid * 2 + 1];
        bool t1 = (d1 < d0 || (d1 == d0 && i1 < i0));
        cand_d[(size_t)(p0 + tid) * 4 + np] = t1 ? d1 : d0;
        cand_i[(size_t)(p0 + tid) * 4 + np] = t1 ? i1 : i0;
    }
}

// ---------------------------------------------------------------------------
// fused: combine 4 candidates -> index + loss partial + sector-efficient
// gather (proven R13/R14 body)
// ---------------------------------------------------------------------------
__global__ void __launch_bounds__(256)
k_out(const float* __restrict__ cb,
      const float* __restrict__ cand_d, const int* __restrict__ cand_i,
      float* __restrict__ out, double* __restrict__ partial) {
    extern __shared__ float qs[];        // [64][257]
    __shared__ int idxs[128];
    __shared__ float sd[128];
    __shared__ double red[256];
    const int tid = threadIdx.x;
    const int w = tid >> 5, l = tid & 31;
    const int blk = blockIdx.x;
    const int b = blk >> 5, hw0 = (blk & 31) << 7;

    if (tid < 128) {
        const int pp = blk * 128 + tid;   // flat pixel index
        size_t base = (size_t)pp * 4;
        float bdv = cand_d[base]; int biv = cand_i[base];
        #pragma unroll
        for (int t = 1; t < 4; ++t) {
            float d = cand_d[base + t]; int i = cand_i[base + t];
            if (d < bdv || (d == bdv && i < biv)) { bdv = d; biv = i; }
        }
        idxs[tid] = biv;
        sd[tid] = bdv;
        out[IDX_OFF + pp] = (float)biv;
    }
    __syncthreads();

    red[tid] = (tid < 128) ? (double)sd[tid] : 0.0;
    __syncthreads();
    #pragma unroll
    for (int s = 128; s > 0; s >>= 1) {
        if (tid < s) red[tid] += red[tid + s];
        __syncthreads();
    }
    if (tid == 0) partial[blk] = red[0];

    float* outb = out + ((size_t)b << 20);
    #pragma unroll
    for (int h = 0; h < 2; ++h) {
        #pragma unroll
        for (int r = 0; r < 8; ++r) {
            const int lp = w * 8 + r;
            const float* row = cb + (size_t)idxs[h * 64 + lp] * CDIM;
            float* q = qs + lp * 257;
            #pragma unroll
            for (int j = 0; j < 8; ++j)
                q[l + 32 * j] = row[l + 32 * j];
        }
        __syncthreads();
        for (int t = tid; t < 4096; t += 256) {
            int d = t >> 4, p4 = t & 15;
            float4 v;
            v.x = qs[(4 * p4 + 0) * 257 + d];
            v.y = qs[(4 * p4 + 1) * 257 + d];
            v.z = qs[(4 * p4 + 2) * 257 + d];
            v.w = qs[(4 * p4 + 3) * 257 + d];
            *(float4*)(outb + (size_t)d * HW + hw0 + h * 64 + 4 * p4) = v;
        }
        __syncthreads();
    }
}

__global__ void k_final(const double* __restrict__ partial, float* __restrict__ out) {
    __shared__ double red[256];
    int tid = threadIdx.x;
    red[tid] = partial[tid] + partial[tid + 256];
    __syncthreads();
    #pragma unroll
    for (int s = 128; s > 0; s >>= 1) {
        if (tid < s) red[tid] += red[tid + s];
        __syncthreads();
    }
    if (tid == 0) {
        double mse = red[0] / ((double)NPIX * (double)CDIM);
        out[LOSS_OFF] = (float)(1.25 * mse);
    }
}

// ---------------------------------------------------------------------------
extern "C" void kernel_launch(void* const* d_in, const int* in_sizes, int n_in,
                              void* d_out, int out_size) {
    (void)in_sizes; (void)n_in; (void)out_size;
    const float* in = (const float*)d_in[0];
    const float* cb = (const float*)d_in[1];
    float* out = (float*)d_out;

    __half* A_p; __half* B_p;
    float *s1_p, *s2_p, *cd_p; int* ci_p; double* part_p;
    cudaGetSymbolAddress((void**)&A_p,   g_A);
    cudaGetSymbolAddress((void**)&B_p,   g_B);
    cudaGetSymbolAddress((void**)&s1_p,  g_s1);
    cudaGetSymbolAddress((void**)&s2_p,  g_s2);
    cudaGetSymbolAddress((void**)&cd_p,  g_cand_d);
    cudaGetSymbolAddress((void**)&ci_p,  g_cand_i);
    cudaGetSymbolAddress((void**)&part_p, g_partial);

    const int smem_a = 256 * 37 * 4;             // 37888
    const int smem_g = 4096 + 3 * 32768;         // 102400 -> 2 CTAs/SM
    const int smem_o = 64 * 257 * 4;             // 65792
    cudaFuncSetAttribute(k_split_a, cudaFuncAttributeMaxDynamicSharedMemorySize, smem_a);
    cudaFuncSetAttribute(k_gemm,    cudaFuncAttributeMaxDynamicSharedMemorySize, smem_g);
    cudaFuncSetAttribute(k_out,     cudaFuncAttributeMaxDynamicSharedMemorySize, smem_o);

    k_split_b<<<128, 256>>>(cb, B_p, s2_p);                           // idx 0
    k_split_a<<<2048, 256, smem_a>>>(in, A_p, s1_p);                  // idx 1
    k_nop<<<1, 32>>>();                                               // idx 2
    k_gemm<<<2048, 128, smem_g>>>(A_p, B_p, s1_p, s2_p, cd_p, ci_p);  // idx 3 -> ncu
    k_out<<<NTILES, 256, smem_o>>>(cb, cd_p, ci_p, out, part_p);      // idx 4
    k_final<<<1, 256>>>(part_p, out);                                 // idx 5
}

// round 16
// speedup vs baseline: 1.1084x; 1.0403x over previous
#include <cuda_runtime.h>
#include <cuda_fp16.h>
#include <cstdint>

#define CDIM 256
#define HW 4096
#define NPIX 65536
#define NTILES 512
#define KCODES 1024
#define LOSS_OFF 16777216
#define IDX_OFF  16777217

// scratch (__device__ globals; no cudaMalloc allowed)
__device__ __half  g_A[(size_t)NPIX * 512];     // [pixel][xh(256)|xl(256)]   64 MB
__device__ __half  g_B[(size_t)KCODES * 768];   // [code][Eh|Eh|El]           1.5 MB
__device__ float   g_s1[NPIX];
__device__ float   g_s2[KCODES];
__device__ float   g_cand_d[NPIX * 8];
__device__ int     g_cand_i[NPIX * 8];
__device__ double  g_partial[NTILES];
__device__ int     g_done;

__device__ __forceinline__ uint32_t smem_u32(const void* p) {
    uint32_t a;
    asm("{ .reg .u64 t; cvta.to.shared.u64 t, %1; cvt.u32.u64 %0, t; }" : "=r"(a) : "l"(p));
    return a;
}

#define LDSM4(r0, r1, r2, r3, addr) \
    asm volatile("ldmatrix.sync.aligned.m8n8.x4.shared.b16 {%0,%1,%2,%3}, [%4];" \
        : "=r"(r0), "=r"(r1), "=r"(r2), "=r"(r3) : "r"(addr))

#define MMA16816(c0, c1, c2, c3, a0, a1, a2, a3, b0, b1) \
    asm volatile("mma.sync.aligned.m16n8k16.row.col.f32.f16.f16.f32 " \
        "{%0,%1,%2,%3}, {%4,%5,%6,%7}, {%8,%9}, {%0,%1,%2,%3};" \
        : "+f"(c0), "+f"(c1), "+f"(c2), "+f"(c3) \
        : "r"(a0), "r"(a1), "r"(a2), "r"(a3), "r"(b0), "r"(b1))

__global__ void k_nop() {}

// ---------------------------------------------------------------------------
// fused prep: blocks 0..127 -> split_b (proven R11 body);
//             blocks 128..2175 -> split_a (proven R13 body).
// Block 0 thread 0 also resets the done-counter (graph-replay safe).
// ---------------------------------------------------------------------------
__global__ void __launch_bounds__(256)
k_prep(const float* __restrict__ in, const float* __restrict__ cb,
       __half* __restrict__ A_, __half* __restrict__ B_,
       float* __restrict__ s1g, float* __restrict__ s2g,
       int* __restrict__ done) {
    const int tid = threadIdx.x;
    if (blockIdx.x < 128) {
        if (blockIdx.x == 0 && tid == 0) *done = 0;
        // ---- split_b body (proven R11) ----
        const int gw = (blockIdx.x * 256 + tid) >> 5;   // global warp = code
        const int l  = tid & 31;
        if (gw >= KCODES) return;
        const float* row = cb + (size_t)gw * CDIM;
        __half* o = B_ + (size_t)gw * 768;
        float e[8];
        float s = 0.f;
        #pragma unroll
        for (int j = 0; j < 8; ++j) {
            e[j] = row[l + 32 * j];
            s += e[j] * e[j];
        }
        #pragma unroll
        for (int off = 16; off > 0; off >>= 1)
            s += __shfl_down_sync(0xffffffffu, s, off);
        if (l == 0) s2g[gw] = s;
        #pragma unroll
        for (int j = 0; j < 8; ++j) {
            int d = l + 32 * j;
            float E = e[j] * 1024.0f;
            __half eh = __float2half_rn(E);
            __half el = __float2half_rn(E - __half2float(eh));
            o[d] = eh; o[256 + d] = eh; o[512 + d] = el;
        }
        return;
    }

    // ---- split_a body (proven R13) ----
    extern __shared__ float xs[];   // [256 d][stride 37]
    const int blk = blockIdx.x - 128;           // 2048 blocks of 32 pixels
    const int b = blk >> 7, hw0 = (blk & 127) << 5;
    const float* inb = in + ((size_t)b << 20);

    for (int t = tid; t < 256 * 8; t += 256) {
        int d = t >> 3, p4 = t & 7;
        float4 v = *(const float4*)(inb + (size_t)d * HW + hw0 + p4 * 4);
        float* dst = xs + d * 37 + p4 * 4;
        dst[0] = v.x; dst[1] = v.y; dst[2] = v.z; dst[3] = v.w;
    }
    __syncthreads();

    if (tid < 32) {   // sequential-d order -> bit-identical s1
        float s = 0.f;
        for (int d = 0; d < CDIM; ++d) { float v = xs[d * 37 + tid]; s += v * v; }
        s1g[blk * 32 + tid] = s;
    }

    const int h = tid >> 7, t = tid & 127;
    const int d0 = 2 * t;
    for (int i = 16 * h; i < 16 * h + 16; ++i) {
        float x0 = xs[d0 * 37 + i];
        float x1 = xs[(d0 + 1) * 37 + i];
        __half xh0 = __float2half_rn(x0);
        __half xh1 = __float2half_rn(x1);
        __half xl0 = __float2half_rn(x0 - __half2float(xh0));
        __half xl1 = __float2half_rn(x1 - __half2float(xh1));
        size_t row = ((size_t)(blk * 32 + i)) << 9;   // *512
        *(__half2*)(A_ + row + d0)       = __halves2half2(xh0, xh1);
        *(__half2*)(A_ + row + 256 + d0) = __halves2half2(xl0, xl1);
    }
}

// ---------------------------------------------------------------------------
// HMMA GEMM tile (PROVEN R13, byte-identical): 128 px x 128 codes, nt=blk&7,
// 4 warps, 64x64 warp tile, 3-stage XOR-swizzled pipeline, one sync/chunk.
// ---------------------------------------------------------------------------
__device__ __forceinline__ void load_chunk3(uint32_t st, const char* Ag, const char* Bg,
                                            int p0, int nt, int kc, int tid) {
    const size_t aoff = (size_t)(kc & 7) * 128;
    const size_t boff = (size_t)kc * 128;
    #pragma unroll
    for (int i = 0; i < 8; ++i) {
        int o = tid + 128 * i;           // 0..1023
        int row = o >> 3, seg = (o & 7) * 16;
        const char* src = Ag + ((size_t)(p0 + row) << 10) + aoff + seg;
        uint32_t dst = st + row * 128 + (seg ^ ((row & 7) << 4));
        asm volatile("cp.async.cg.shared.global [%0], [%1], 16;" :: "r"(dst), "l"(src));
    }
    #pragma unroll
    for (int i = 0; i < 8; ++i) {
        int o = tid + 128 * i;
        int row = o >> 3, seg = (o & 7) * 16;
        const char* src = Bg + (size_t)(nt * 128 + row) * 1536 + boff + seg;
        uint32_t dst = st + 16384 + row * 128 + (seg ^ ((row & 7) << 4));
        asm volatile("cp.async.cg.shared.global [%0], [%1], 16;" :: "r"(dst), "l"(src));
    }
}

__global__ void __launch_bounds__(128, 2)
k_gemm(const __half* __restrict__ Ah, const __half* __restrict__ Bh,
       const float* __restrict__ s1g, const float* __restrict__ s2g,
       float* __restrict__ cand_d, int* __restrict__ cand_i) {
    extern __shared__ char sm[];
    uint32_t sb = smem_u32(sm);
    float* rd = (float*)sm;
    int*   ri = (int*)(sm + 1024);
    float* s2s = (float*)(sm + 2048);
    const uint32_t stg = sb + 4096;

    const int tid = threadIdx.x, lane = tid & 31, wid = tid >> 5;
    const int warp_m = wid & 1, warp_n = wid >> 1;    // 2M x 2N warp grid
    const int m0 = warp_m * 64, n0 = warp_n * 64;
    const int blk = blockIdx.x, pb = blk >> 3, nt = blk & 7;   // 8 code tiles
    const int p0 = pb * 128;
    const char* Ag = (const char*)Ah;
    const char* Bg = (const char*)Bh;

    s2s[tid] = s2g[nt * 128 + tid];

    const int rA = (lane & 7) + ((lane >> 3) & 1) * 8;
    const int cA = (lane >> 4) * 16;
    const int mA = (rA & 7) << 4;
    uint32_t arow[4];
    #pragma unroll
    for (int f = 0; f < 4; ++f) arow[f] = (uint32_t)(m0 + f * 16 + rA) * 128;
    const int rB = (lane & 7) + ((lane >> 4) << 3);
    const int cB = ((lane >> 3) & 1) * 16;
    const int mB = (rB & 7) << 4;
    uint32_t brow[4];
    #pragma unroll
    for (int g = 0; g < 4; ++g) brow[g] = (uint32_t)(n0 + g * 16 + rB) * 128;

    float s1v[8];
    #pragma unroll
    for (int s = 0; s < 8; ++s)
        s1v[s] = s1g[p0 + m0 + (s >> 1) * 16 + (lane >> 2) + (s & 1) * 8];

    float c[4][8][4];
    #pragma unroll
    for (int mf = 0; mf < 4; ++mf)
        #pragma unroll
        for (int j = 0; j < 8; ++j)
            #pragma unroll
            for (int q = 0; q < 4; ++q) c[mf][j][q] = 0.f;

    load_chunk3(stg,         Ag, Bg, p0, nt, 0, tid);
    asm volatile("cp.async.commit_group;" ::: "memory");
    load_chunk3(stg + 32768, Ag, Bg, p0, nt, 1, tid);
    asm volatile("cp.async.commit_group;" ::: "memory");

    for (int kc = 0; kc < 12; ++kc) {
        if (kc < 11) asm volatile("cp.async.wait_group 1;" ::: "memory");
        else         asm volatile("cp.async.wait_group 0;" ::: "memory");
        __syncthreads();
        if (kc + 2 < 12) {
            load_chunk3(stg + ((kc + 2) % 3) * 32768, Ag, Bg, p0, nt, kc + 2, tid);
            asm volatile("cp.async.commit_group;" ::: "memory");
        }

        const uint32_t sA = stg + (kc % 3) * 32768;
        const uint32_t sB = sA + 16384;
        #pragma unroll
        for (int ks = 0; ks < 4; ++ks) {
            const uint32_t colA = (uint32_t)((cA + ks * 32) ^ mA);
            const uint32_t colB = (uint32_t)((cB + ks * 32) ^ mB);
            uint32_t a[4][4], bf[4][4];
            #pragma unroll
            for (int f = 0; f < 4; ++f)
                LDSM4(a[f][0], a[f][1], a[f][2], a[f][3], sA + arow[f] + colA);
            #pragma unroll
            for (int g = 0; g < 4; ++g)
                LDSM4(bf[g][0], bf[g][1], bf[g][2], bf[g][3], sB + brow[g] + colB);

            #pragma unroll
            for (int f = 0; f < 4; ++f) {
                #pragma unroll
                for (int g = 0; g < 4; ++g) {
                    MMA16816(c[f][2*g][0], c[f][2*g][1], c[f][2*g][2], c[f][2*g][3],
                             a[f][0], a[f][1], a[f][2], a[f][3], bf[g][0], bf[g][1]);
                    MMA16816(c[f][2*g+1][0], c[f][2*g+1][1], c[f][2*g+1][2], c[f][2*g+1][3],
                             a[f][0], a[f][1], a[f][2], a[f][3], bf[g][2], bf[g][3]);
                }
            }
        }
    }

    const float SC = 0.001953125f;   // 2^-9
    float bd[8];
    int   bi[8];
    #pragma unroll
    for (int s = 0; s < 8; ++s) { bd[s] = 3.4e38f; bi[s] = 0; }
    #pragma unroll
    for (int mf = 0; mf < 4; ++mf) {
        #pragma unroll
        for (int j = 0; j < 8; ++j) {
            const int nl = n0 + j * 8 + ((lane & 3) << 1);
            const float s2a = s2s[nl], s2b = s2s[nl + 1];
            const int sl0 = mf * 2, sl1 = mf * 2 + 1;
            float d0 = (s1v[sl0] + s2a) - c[mf][j][0] * SC;
            float d1 = (s1v[sl0] + s2b) - c[mf][j][1] * SC;
            float d2 = (s1v[sl1] + s2a) - c[mf][j][2] * SC;
            float d3 = (s1v[sl1] + s2b) - c[mf][j][3] * SC;
            if (d0 < bd[sl0]) { bd[sl0] = d0; bi[sl0] = nl; }
            if (d1 < bd[sl0]) { bd[sl0] = d1; bi[sl0] = nl + 1; }
            if (d2 < bd[sl1]) { bd[sl1] = d2; bi[sl1] = nl; }
            if (d3 < bd[sl1]) { bd[sl1] = d3; bi[sl1] = nl + 1; }
        }
    }
    #pragma unroll
    for (int s = 0; s < 8; ++s) {
        #pragma unroll
        for (int off = 1; off <= 2; off <<= 1) {
            float od = __shfl_xor_sync(0xffffffffu, bd[s], off);
            int   oi = __shfl_xor_sync(0xffffffffu, bi[s], off);
            if (od < bd[s] || (od == bd[s] && oi < bi[s])) { bd[s] = od; bi[s] = oi; }
        }
    }
    __syncthreads();
    if ((lane & 3) == 0) {
        #pragma unroll
        for (int s = 0; s < 8; ++s) {
            int row = m0 + (s >> 1) * 16 + (lane >> 2) + (s & 1) * 8;
            rd[row * 2 + warp_n] = bd[s];
            ri[row * 2 + warp_n] = bi[s];
        }
    }
    __syncthreads();
    {
        float d0 = rd[tid * 2], d1 = rd[tid * 2 + 1];
        int i0 = ri[tid * 2], i1 = ri[tid * 2 + 1];
        bool t1 = (d1 < d0 || (d1 == d0 && i1 < i0));
        cand_d[(size_t)(p0 + tid) * 8 + nt] = t1 ? d1 : d0;
        cand_i[(size_t)(p0 + tid) * 8 + nt] = nt * 128 + (t1 ? i1 : i0);
    }
}

// ---------------------------------------------------------------------------
// fused: combine 8 candidates -> index + loss partial + sector-efficient
// gather (proven R13 body) + last-block final loss reduce (R13 k_final tree).
// ---------------------------------------------------------------------------
__global__ void __launch_bounds__(256)
k_out(const float* __restrict__ cb,
      const float* __restrict__ cand_d, const int* __restrict__ cand_i,
      float* __restrict__ out, double* __restrict__ partial,
      int* __restrict__ done) {
    extern __shared__ float qs[];        // [64][257]
    __shared__ int idxs[128];
    __shared__ float sd[128];
    __shared__ double red[256];
    __shared__ int is_last;
    const int tid = threadIdx.x;
    const int w = tid >> 5, l = tid & 31;
    const int blk = blockIdx.x;
    const int b = blk >> 5, hw0 = (blk & 31) << 7;

    if (tid < 128) {
        const int pp = blk * 128 + tid;   // flat pixel index
        size_t base = (size_t)pp * 8;
        float bdv = cand_d[base]; int biv = cand_i[base];
        #pragma unroll
        for (int t = 1; t < 8; ++t) {
            float d = cand_d[base + t]; int i = cand_i[base + t];
            if (d < bdv || (d == bdv && i < biv)) { bdv = d; biv = i; }
        }
        idxs[tid] = biv;
        sd[tid] = bdv;
        out[IDX_OFF + pp] = (float)biv;
    }
    __syncthreads();

    red[tid] = (tid < 128) ? (double)sd[tid] : 0.0;
    __syncthreads();
    #pragma unroll
    for (int s = 128; s > 0; s >>= 1) {
        if (tid < s) red[tid] += red[tid + s];
        __syncthreads();
    }
    if (tid == 0) {
        partial[blk] = red[0];
        __threadfence();
        is_last = (atomicAdd(done, 1) == NTILES - 1);
    }

    float* outb = out + ((size_t)b << 20);
    #pragma unroll
    for (int h = 0; h < 2; ++h) {
        #pragma unroll
        for (int r = 0; r < 8; ++r) {
            const int lp = w * 8 + r;
            const float* row = cb + (size_t)idxs[h * 64 + lp] * CDIM;
            float* q = qs + lp * 257;
            #pragma unroll
            for (int j = 0; j < 8; ++j)
                q[l + 32 * j] = row[l + 32 * j];
        }
        __syncthreads();
        for (int t = tid; t < 4096; t += 256) {
            int d = t >> 4, p4 = t & 15;
            float4 v;
            v.x = qs[(4 * p4 + 0) * 257 + d];
            v.y = qs[(4 * p4 + 1) * 257 + d];
            v.z = qs[(4 * p4 + 2) * 257 + d];
            v.w = qs[(4 * p4 + 3) * 257 + d];
            *(float4*)(outb + (size_t)d * HW + hw0 + h * 64 + 4 * p4) = v;
        }
        __syncthreads();
    }

    // final loss reduce in the last-arriving block (exact R13 k_final tree)
    if (is_last) {
        __threadfence();
        red[tid] = partial[tid] + partial[tid + 256];
        __syncthreads();
        #pragma unroll
        for (int s = 128; s > 0; s >>= 1) {
            if (tid < s) red[tid] += red[tid + s];
            __syncthreads();
        }
        if (tid == 0) {
            double mse = red[0] / ((double)NPIX * (double)CDIM);
            out[LOSS_OFF] = (float)(1.25 * mse);
        }
    }
}

// ---------------------------------------------------------------------------
extern "C" void kernel_launch(void* const* d_in, const int* in_sizes, int n_in,
                              void* d_out, int out_size) {
    (void)in_sizes; (void)n_in; (void)out_size;
    const float* in = (const float*)d_in[0];
    const float* cb = (const float*)d_in[1];
    float* out = (float*)d_out;

    __half* A_p; __half* B_p;
    float *s1_p, *s2_p, *cd_p; int* ci_p; double* part_p; int* done_p;
    cudaGetSymbolAddress((void**)&A_p,   g_A);
    cudaGetSymbolAddress((void**)&B_p,   g_B);
    cudaGetSymbolAddress((void**)&s1_p,  g_s1);
    cudaGetSymbolAddress((void**)&s2_p,  g_s2);
    cudaGetSymbolAddress((void**)&cd_p,  g_cand_d);
    cudaGetSymbolAddress((void**)&ci_p,  g_cand_i);
    cudaGetSymbolAddress((void**)&part_p, g_partial);
    cudaGetSymbolAddress((void**)&done_p, g_done);

    const int smem_p = 256 * 37 * 4;             // 37888
    const int smem_g = 4096 + 3 * 32768;         // 102400 -> 2 CTAs/SM
    const int smem_o = 64 * 257 * 4;             // 65792
    cudaFuncSetAttribute(k_prep, cudaFuncAttributeMaxDynamicSharedMemorySize, smem_p);
    cudaFuncSetAttribute(k_gemm, cudaFuncAttributeMaxDynamicSharedMemorySize, smem_g);
    cudaFuncSetAttribute(k_out,  cudaFuncAttributeMaxDynamicSharedMemorySize, smem_o);

    k_prep<<<2176, 256, smem_p>>>(in, cb, A_p, B_p, s1_p, s2_p, done_p);  // idx 0
    k_nop<<<1, 32>>>();                                                   // idx 1
    k_nop<<<1, 32>>>();                                                   // idx 2
    k_gemm<<<4096, 128, smem_g>>>(A_p, B_p, s1_p, s2_p, cd_p, ci_p);      // idx 3 -> ncu
    k_out<<<NTILES, 256, smem_o>>>(cb, cd_p, ci_p, out, part_p, done_p);  // idx 4
}

// round 17
// speedup vs baseline: 1.1160x; 1.0069x over previous
#include <cuda_runtime.h>
#include <cuda_fp16.h>
#include <cstdint>

#define CDIM 256
#define HW 4096
#define NPIX 65536
#define KCODES 1024
#define NPARTS 1024
#define LOSS_OFF 16777216
#define IDX_OFF  16777217

// scratch (__device__ globals; no cudaMalloc allowed)
__device__ __half  g_A[(size_t)NPIX * 512];     // [pixel][xh(256)|xl(256)]   64 MB
__device__ __half  g_B[(size_t)KCODES * 768];   // [code][Eh|Eh|El]           1.5 MB
__device__ float   g_s1[NPIX];
__device__ float   g_s2[KCODES];
__device__ float   g_cand_d[NPIX * 8];
__device__ int     g_cand_i[NPIX * 8];
__device__ double  g_partial[NPARTS];
__device__ int     g_done;

__device__ __forceinline__ uint32_t smem_u32(const void* p) {
    uint32_t a;
    asm("{ .reg .u64 t; cvta.to.shared.u64 t, %1; cvt.u32.u64 %0, t; }" : "=r"(a) : "l"(p));
    return a;
}

#define LDSM4(r0, r1, r2, r3, addr) \
    asm volatile("ldmatrix.sync.aligned.m8n8.x4.shared.b16 {%0,%1,%2,%3}, [%4];" \
        : "=r"(r0), "=r"(r1), "=r"(r2), "=r"(r3) : "r"(addr))

#define MMA16816(c0, c1, c2, c3, a0, a1, a2, a3, b0, b1) \
    asm volatile("mma.sync.aligned.m16n8k16.row.col.f32.f16.f16.f32 " \
        "{%0,%1,%2,%3}, {%4,%5,%6,%7}, {%8,%9}, {%0,%1,%2,%3};" \
        : "+f"(c0), "+f"(c1), "+f"(c2), "+f"(c3) \
        : "r"(a0), "r"(a1), "r"(a2), "r"(a3), "r"(b0), "r"(b1))

// ---------------------------------------------------------------------------
// fused prep: blocks 0..127 -> split_b (proven R11 body);
//             blocks 128..2175 -> split_a (proven R13 body).
// Block 0 thread 0 also resets the done-counter (graph-replay safe).
// ---------------------------------------------------------------------------
__global__ void __launch_bounds__(256)
k_prep(const float* __restrict__ in, const float* __restrict__ cb,
       __half* __restrict__ A_, __half* __restrict__ B_,
       float* __restrict__ s1g, float* __restrict__ s2g,
       int* __restrict__ done) {
    const int tid = threadIdx.x;
    if (blockIdx.x < 128) {
        if (blockIdx.x == 0 && tid == 0) *done = 0;
        // ---- split_b body (proven R11) ----
        const int gw = (blockIdx.x * 256 + tid) >> 5;   // global warp = code
        const int l  = tid & 31;
        if (gw >= KCODES) return;
        const float* row = cb + (size_t)gw * CDIM;
        __half* o = B_ + (size_t)gw * 768;
        float e[8];
        float s = 0.f;
        #pragma unroll
        for (int j = 0; j < 8; ++j) {
            e[j] = row[l + 32 * j];
            s += e[j] * e[j];
        }
        #pragma unroll
        for (int off = 16; off > 0; off >>= 1)
            s += __shfl_down_sync(0xffffffffu, s, off);
        if (l == 0) s2g[gw] = s;
        #pragma unroll
        for (int j = 0; j < 8; ++j) {
            int d = l + 32 * j;
            float E = e[j] * 1024.0f;
            __half eh = __float2half_rn(E);
            __half el = __float2half_rn(E - __half2float(eh));
            o[d] = eh; o[256 + d] = eh; o[512 + d] = el;
        }
        return;
    }

    // ---- split_a body (proven R13) ----
    extern __shared__ float xs[];   // [256 d][stride 37]
    const int blk = blockIdx.x - 128;           // 2048 blocks of 32 pixels
    const int b = blk >> 7, hw0 = (blk & 127) << 5;
    const float* inb = in + ((size_t)b << 20);

    for (int t = tid; t < 256 * 8; t += 256) {
        int d = t >> 3, p4 = t & 7;
        float4 v = *(const float4*)(inb + (size_t)d * HW + hw0 + p4 * 4);
        float* dst = xs + d * 37 + p4 * 4;
        dst[0] = v.x; dst[1] = v.y; dst[2] = v.z; dst[3] = v.w;
    }
    __syncthreads();

    if (tid < 32) {   // sequential-d order -> bit-identical s1
        float s = 0.f;
        for (int d = 0; d < CDIM; ++d) { float v = xs[d * 37 + tid]; s += v * v; }
        s1g[blk * 32 + tid] = s;
    }

    const int h = tid >> 7, t = tid & 127;
    const int d0 = 2 * t;
    for (int i = 16 * h; i < 16 * h + 16; ++i) {
        float x0 = xs[d0 * 37 + i];
        float x1 = xs[(d0 + 1) * 37 + i];
        __half xh0 = __float2half_rn(x0);
        __half xh1 = __float2half_rn(x1);
        __half xl0 = __float2half_rn(x0 - __half2float(xh0));
        __half xl1 = __float2half_rn(x1 - __half2float(xh1));
        size_t row = ((size_t)(blk * 32 + i)) << 9;   // *512
        *(__half2*)(A_ + row + d0)       = __halves2half2(xh0, xh1);
        *(__half2*)(A_ + row + 256 + d0) = __halves2half2(xl0, xl1);
    }
}

// ---------------------------------------------------------------------------
// HMMA GEMM tile (PROVEN R13, byte-identical): 128 px x 128 codes, nt=blk&7,
// 4 warps, 64x64 warp tile, 3-stage XOR-swizzled pipeline, one sync/chunk.
// ---------------------------------------------------------------------------
__device__ __forceinline__ void load_chunk3(uint32_t st, const char* Ag, const char* Bg,
                                            int p0, int nt, int kc, int tid) {
    const size_t aoff = (size_t)(kc & 7) * 128;
    const size_t boff = (size_t)kc * 128;
    #pragma unroll
    for (int i = 0; i < 8; ++i) {
        int o = tid + 128 * i;           // 0..1023
        int row = o >> 3, seg = (o & 7) * 16;
        const char* src = Ag + ((size_t)(p0 + row) << 10) + aoff + seg;
        uint32_t dst = st + row * 128 + (seg ^ ((row & 7) << 4));
        asm volatile("cp.async.cg.shared.global [%0], [%1], 16;" :: "r"(dst), "l"(src));
    }
    #pragma unroll
    for (int i = 0; i < 8; ++i) {
        int o = tid + 128 * i;
        int row = o >> 3, seg = (o & 7) * 16;
        const char* src = Bg + (size_t)(nt * 128 + row) * 1536 + boff + seg;
        uint32_t dst = st + 16384 + row * 128 + (seg ^ ((row & 7) << 4));
        asm volatile("cp.async.cg.shared.global [%0], [%1], 16;" :: "r"(dst), "l"(src));
    }
}

__global__ void __launch_bounds__(128, 2)
k_gemm(const __half* __restrict__ Ah, const __half* __restrict__ Bh,
       const float* __restrict__ s1g, const float* __restrict__ s2g,
       float* __restrict__ cand_d, int* __restrict__ cand_i) {
    extern __shared__ char sm[];
    uint32_t sb = smem_u32(sm);
    float* rd = (float*)sm;
    int*   ri = (int*)(sm + 1024);
    float* s2s = (float*)(sm + 2048);
    const uint32_t stg = sb + 4096;

    const int tid = threadIdx.x, lane = tid & 31, wid = tid >> 5;
    const int warp_m = wid & 1, warp_n = wid >> 1;    // 2M x 2N warp grid
    const int m0 = warp_m * 64, n0 = warp_n * 64;
    const int blk = blockIdx.x, pb = blk >> 3, nt = blk & 7;   // 8 code tiles
    const int p0 = pb * 128;
    const char* Ag = (const char*)Ah;
    const char* Bg = (const char*)Bh;

    s2s[tid] = s2g[nt * 128 + tid];

    const int rA = (lane & 7) + ((lane >> 3) & 1) * 8;
    const int cA = (lane >> 4) * 16;
    const int mA = (rA & 7) << 4;
    uint32_t arow[4];
    #pragma unroll
    for (int f = 0; f < 4; ++f) arow[f] = (uint32_t)(m0 + f * 16 + rA) * 128;
    const int rB = (lane & 7) + ((lane >> 4) << 3);
    const int cB = ((lane >> 3) & 1) * 16;
    const int mB = (rB & 7) << 4;
    uint32_t brow[4];
    #pragma unroll
    for (int g = 0; g < 4; ++g) brow[g] = (uint32_t)(n0 + g * 16 + rB) * 128;

    float s1v[8];
    #pragma unroll
    for (int s = 0; s < 8; ++s)
        s1v[s] = s1g[p0 + m0 + (s >> 1) * 16 + (lane >> 2) + (s & 1) * 8];

    float c[4][8][4];
    #pragma unroll
    for (int mf = 0; mf < 4; ++mf)
        #pragma unroll
        for (int j = 0; j < 8; ++j)
            #pragma unroll
            for (int q = 0; q < 4; ++q) c[mf][j][q] = 0.f;

    load_chunk3(stg,         Ag, Bg, p0, nt, 0, tid);
    asm volatile("cp.async.commit_group;" ::: "memory");
    load_chunk3(stg + 32768, Ag, Bg, p0, nt, 1, tid);
    asm volatile("cp.async.commit_group;" ::: "memory");

    for (int kc = 0; kc < 12; ++kc) {
        if (kc < 11) asm volatile("cp.async.wait_group 1;" ::: "memory");
        else         asm volatile("cp.async.wait_group 0;" ::: "memory");
        __syncthreads();
        if (kc + 2 < 12) {
            load_chunk3(stg + ((kc + 2) % 3) * 32768, Ag, Bg, p0, nt, kc + 2, tid);
            asm volatile("cp.async.commit_group;" ::: "memory");
        }

        const uint32_t sA = stg + (kc % 3) * 32768;
        const uint32_t sB = sA + 16384;
        #pragma unroll
        for (int ks = 0; ks < 4; ++ks) {
            const uint32_t colA = (uint32_t)((cA + ks * 32) ^ mA);
            const uint32_t colB = (uint32_t)((cB + ks * 32) ^ mB);
            uint32_t a[4][4], bf[4][4];
            #pragma unroll
            for (int f = 0; f < 4; ++f)
                LDSM4(a[f][0], a[f][1], a[f][2], a[f][3], sA + arow[f] + colA);
            #pragma unroll
            for (int g = 0; g < 4; ++g)
                LDSM4(bf[g][0], bf[g][1], bf[g][2], bf[g][3], sB + brow[g] + colB);

            #pragma unroll
            for (int f = 0; f < 4; ++f) {
                #pragma unroll
                for (int g = 0; g < 4; ++g) {
                    MMA16816(c[f][2*g][0], c[f][2*g][1], c[f][2*g][2], c[f][2*g][3],
                             a[f][0], a[f][1], a[f][2], a[f][3], bf[g][0], bf[g][1]);
                    MMA16816(c[f][2*g+1][0], c[f][2*g+1][1], c[f][2*g+1][2], c[f][2*g+1][3],
                             a[f][0], a[f][1], a[f][2], a[f][3], bf[g][2], bf[g][3]);
                }
            }
        }
    }

    const float SC = 0.001953125f;   // 2^-9
    float bd[8];
    int   bi[8];
    #pragma unroll
    for (int s = 0; s < 8; ++s) { bd[s] = 3.4e38f; bi[s] = 0; }
    #pragma unroll
    for (int mf = 0; mf < 4; ++mf) {
        #pragma unroll
        for (int j = 0; j < 8; ++j) {
            const int nl = n0 + j * 8 + ((lane & 3) << 1);
            const float s2a = s2s[nl], s2b = s2s[nl + 1];
            const int sl0 = mf * 2, sl1 = mf * 2 + 1;
            float d0 = (s1v[sl0] + s2a) - c[mf][j][0] * SC;
            float d1 = (s1v[sl0] + s2b) - c[mf][j][1] * SC;
            float d2 = (s1v[sl1] + s2a) - c[mf][j][2] * SC;
            float d3 = (s1v[sl1] + s2b) - c[mf][j][3] * SC;
            if (d0 < bd[sl0]) { bd[sl0] = d0; bi[sl0] = nl; }
            if (d1 < bd[sl0]) { bd[sl0] = d1; bi[sl0] = nl + 1; }
            if (d2 < bd[sl1]) { bd[sl1] = d2; bi[sl1] = nl; }
            if (d3 < bd[sl1]) { bd[sl1] = d3; bi[sl1] = nl + 1; }
        }
    }
    #pragma unroll
    for (int s = 0; s < 8; ++s) {
        #pragma unroll
        for (int off = 1; off <= 2; off <<= 1) {
            float od = __shfl_xor_sync(0xffffffffu, bd[s], off);
            int   oi = __shfl_xor_sync(0xffffffffu, bi[s], off);
            if (od < bd[s] || (od == bd[s] && oi < bi[s])) { bd[s] = od; bi[s] = oi; }
        }
    }
    __syncthreads();
    if ((lane & 3) == 0) {
        #pragma unroll
        for (int s = 0; s < 8; ++s) {
            int row = m0 + (s >> 1) * 16 + (lane >> 2) + (s & 1) * 8;
            rd[row * 2 + warp_n] = bd[s];
            ri[row * 2 + warp_n] = bi[s];
        }
    }
    __syncthreads();
    {
        float d0 = rd[tid * 2], d1 = rd[tid * 2 + 1];
        int i0 = ri[tid * 2], i1 = ri[tid * 2 + 1];
        bool t1 = (d1 < d0 || (d1 == d0 && i1 < i0));
        cand_d[(size_t)(p0 + tid) * 8 + nt] = t1 ? d1 : d0;
        cand_i[(size_t)(p0 + tid) * 8 + nt] = nt * 128 + (t1 ? i1 : i0);
    }
}

// ---------------------------------------------------------------------------
// fused finisher, re-tiled to 1024 blocks x 64 pixels (kills 1.15-wave tail):
// combine 8 candidates -> index + loss partial + single-phase sector-efficient
// gather + last-block final loss reduce.
// dynamic smem: qs 64*257*4 = 65792 B
// ---------------------------------------------------------------------------
__global__ void __launch_bounds__(256)
k_out(const float* __restrict__ cb,
      const float* __restrict__ cand_d, const int* __restrict__ cand_i,
      float* __restrict__ out, double* __restrict__ partial,
      int* __restrict__ done) {
    extern __shared__ float qs[];        // [64][257]
    __shared__ int idxs[64];
    __shared__ float sd[64];
    __shared__ double red[256];
    __shared__ int is_last;
    const int tid = threadIdx.x;
    const int w = tid >> 5, l = tid & 31;
    const int blk = blockIdx.x;          // 1024 blocks of 64 pixels
    const int b = blk >> 6, hw0 = (blk & 63) << 6;

    if (tid < 64) {
        const int pp = blk * 64 + tid;   // flat pixel index
        size_t base = (size_t)pp * 8;
        float bdv = cand_d[base]; int biv = cand_i[base];
        #pragma unroll
        for (int t = 1; t < 8; ++t) {
            float d = cand_d[base + t]; int i = cand_i[base + t];
            if (d < bdv || (d == bdv && i < biv)) { bdv = d; biv = i; }
        }
        idxs[tid] = biv;
        sd[tid] = bdv;
        out[IDX_OFF + pp] = (float)biv;
    }
    __syncthreads();

    // loss partial (deterministic double tree over this block's 64 pixels)
    red[tid] = (tid < 64) ? (double)sd[tid] : 0.0;
    __syncthreads();
    #pragma unroll
    for (int s = 128; s > 0; s >>= 1) {
        if (tid < s) red[tid] += red[tid + s];
        __syncthreads();
    }
    if (tid == 0) {
        partial[blk] = red[0];
        __threadfence();
        is_last = (atomicAdd(done, 1) == NPARTS - 1);
    }

    // gather: warp w owns pixels lp = w*8 .. w*8+7 (all 64 in one phase)
    #pragma unroll
    for (int r = 0; r < 8; ++r) {
        const int lp = w * 8 + r;
        const float* row = cb + (size_t)idxs[lp] * CDIM;
        float* q = qs + lp * 257;
        #pragma unroll
        for (int j = 0; j < 8; ++j)
            q[l + 32 * j] = row[l + 32 * j];   // coalesced 128B; bank (lp+l)%32
    }
    __syncthreads();

    // scatter: coalesced float4 stores over the 64 pixels
    float* outb = out + ((size_t)b << 20);
    for (int t = tid; t < 4096; t += 256) {
        int d = t >> 4, p4 = t & 15;
        float4 v;
        v.x = qs[(4 * p4 + 0) * 257 + d];
        v.y = qs[(4 * p4 + 1) * 257 + d];
        v.z = qs[(4 * p4 + 2) * 257 + d];
        v.w = qs[(4 * p4 + 3) * 257 + d];
        *(float4*)(outb + (size_t)d * HW + hw0 + 4 * p4) = v;
    }
    __syncthreads();

    // final loss reduce in the last-arriving block (deterministic tree)
    if (is_last) {
        __threadfence();
        red[tid] = (partial[tid] + partial[tid + 256])
                 + (partial[tid + 512] + partial[tid + 768]);
        __syncthreads();
        #pragma unroll
        for (int s = 128; s > 0; s >>= 1) {
            if (tid < s) red[tid] += red[tid + s];
            __syncthreads();
        }
        if (tid == 0) {
            double mse = red[0] / ((double)NPIX * (double)CDIM);
            out[LOSS_OFF] = (float)(1.25 * mse);
        }
    }
}

// ---------------------------------------------------------------------------
extern "C" void kernel_launch(void* const* d_in, const int* in_sizes, int n_in,
                              void* d_out, int out_size) {
    (void)in_sizes; (void)n_in; (void)out_size;
    const float* in = (const float*)d_in[0];
    const float* cb = (const float*)d_in[1];
    float* out = (float*)d_out;

    __half* A_p; __half* B_p;
    float *s1_p, *s2_p, *cd_p; int* ci_p; double* part_p; int* done_p;
    cudaGetSymbolAddress((void**)&A_p,   g_A);
    cudaGetSymbolAddress((void**)&B_p,   g_B);
    cudaGetSymbolAddress((void**)&s1_p,  g_s1);
    cudaGetSymbolAddress((void**)&s2_p,  g_s2);
    cudaGetSymbolAddress((void**)&cd_p,  g_cand_d);
    cudaGetSymbolAddress((void**)&ci_p,  g_cand_i);
    cudaGetSymbolAddress((void**)&part_p, g_partial);
    cudaGetSymbolAddress((void**)&done_p, g_done);

    const int smem_p = 256 * 37 * 4;             // 37888
    const int smem_g = 4096 + 3 * 32768;         // 102400 -> 2 CTAs/SM
    const int smem_o = 64 * 257 * 4;             // 65792
    cudaFuncSetAttribute(k_prep, cudaFuncAttributeMaxDynamicSharedMemorySize, smem_p);
    cudaFuncSetAttribute(k_gemm, cudaFuncAttributeMaxDynamicSharedMemorySize, smem_g);
    cudaFuncSetAttribute(k_out,  cudaFuncAttributeMaxDynamicSharedMemorySize, smem_o);

    k_prep<<<2176, 256, smem_p>>>(in, cb, A_p, B_p, s1_p, s2_p, done_p);
    k_gemm<<<4096, 128, smem_g>>>(A_p, B_p, s1_p, s2_p, cd_p, ci_p);
    k_out<<<1024, 256, smem_o>>>(cb, cd_p, ci_p, out, part_p, done_p);
}